// round 8
// baseline (speedup 1.0000x reference)
#include <cuda_runtime.h>
#include <cstdint>

// Problem constants (fixed by the reference):
//   B=32768, LMAX=24, M=10, D=300, V=36
#define BB    32768
#define LMAXC 24
#define MC    10
#define D4C   75              // D/4 float4s per (b,m) row
#define ELEMS_PER_CTA 2       // batch elements per CTA
#define CHUNK_F4 (ELEMS_PER_CTA * MC * D4C)   // 1500 float4 = 24000 B

// 320 threads = 10 warps. Warp w computes rows 2w and 2w+1 of the CTA's
// 20-row chunk (2 batch elements, never straddling an element boundary),
// into shared memory. One elected thread then drains the whole 24 KB chunk
// to global with a single cp.async.bulk (UBLKCP) burst.
__global__ __launch_bounds__(320)
void word_emb_kernel(const float4* __restrict__ emb,     // [36, 75] float4
                     const float4* __restrict__ pad,     // [75] float4
                     const int*    __restrict__ tokens,  // [B, 24]
                     const int*    __restrict__ lengths, // [B]
                     float4*       __restrict__ out)     // [B*10, 75] float4
{
    __shared__ float4 buf[CHUNK_F4];                     // 24 KB

    const int tid  = threadIdx.x;
    const int w    = tid >> 5;                           // 0..9
    const int lane = tid & 31;
    const int e    = (w >= 5);                           // element within CTA
    const int b    = blockIdx.x * ELEMS_PER_CTA + e;
    const int m0   = (w - e * 5) * 2;                    // rows m0, m0+1

    const int L = __ldg(lengths + b);                    // warp-uniform
    const int* tok_row = tokens + b * LMAXC;
    float4* s0 = buf + (w * 2) * D4C;                    // row m0; row m0+1 at +75

    if (L < MC) {
        // ---- padding branch
        const float4* p0 = (m0     < L) ? (emb + __ldg(tok_row + m0)     * D4C) : pad;
        const float4* p1 = (m0 + 1 < L) ? (emb + __ldg(tok_row + m0 + 1) * D4C) : pad;

        const float4 v00 = p0[lane];
        const float4 v01 = p0[lane + 32];
        const float4 v10 = p1[lane];
        const float4 v11 = p1[lane + 32];
        s0[lane]            = v00;
        s0[lane + 32]       = v01;
        s0[D4C + lane]      = v10;
        s0[D4C + lane + 32] = v11;
        if (lane < D4C - 64) {
            s0[lane + 64]       = p0[lane + 64];
            s0[D4C + lane + 64] = p1[lane + 64];
        }
    } else {
        // ---- interpolate branch: src = m*(L-1)/9, align_corners (fp32 as ref)
        const float pos0 = (float)(m0 * (L - 1)) / 9.0f;
        const int   lo0  = (int)pos0;
        const int   hi0  = min(lo0 + 1, L - 1);
        const float w0   = pos0 - (float)lo0;
        const float n0   = 1.0f - w0;

        const float pos1 = (float)((m0 + 1) * (L - 1)) / 9.0f;
        const int   lo1  = (int)pos1;
        const int   hi1  = min(lo1 + 1, L - 1);
        const float w1   = pos1 - (float)lo1;
        const float n1   = 1.0f - w1;

        const int tlo0 = __ldg(tok_row + lo0);
        const int thi0 = __ldg(tok_row + hi0);
        const int tlo1 = __ldg(tok_row + lo1);
        const int thi1 = __ldg(tok_row + hi1);
        const float4* ea0 = emb + tlo0 * D4C;
        const float4* eb0 = emb + thi0 * D4C;
        const float4* ea1 = emb + tlo1 * D4C;
        const float4* eb1 = emb + thi1 * D4C;

        // front-batch all main-body loads (8 independent LDG.128)
        const float4 A00 = ea0[lane];
        const float4 B00 = eb0[lane];
        const float4 A01 = ea0[lane + 32];
        const float4 B01 = eb0[lane + 32];
        const float4 A10 = ea1[lane];
        const float4 B10 = eb1[lane];
        const float4 A11 = ea1[lane + 32];
        const float4 B11 = eb1[lane + 32];

        float4 r;
        r.x = A00.x * n0 + B00.x * w0;  r.y = A00.y * n0 + B00.y * w0;
        r.z = A00.z * n0 + B00.z * w0;  r.w = A00.w * n0 + B00.w * w0;
        s0[lane] = r;
        r.x = A01.x * n0 + B01.x * w0;  r.y = A01.y * n0 + B01.y * w0;
        r.z = A01.z * n0 + B01.z * w0;  r.w = A01.w * n0 + B01.w * w0;
        s0[lane + 32] = r;
        r.x = A10.x * n1 + B10.x * w1;  r.y = A10.y * n1 + B10.y * w1;
        r.z = A10.z * n1 + B10.z * w1;  r.w = A10.w * n1 + B10.w * w1;
        s0[D4C + lane] = r;
        r.x = A11.x * n1 + B11.x * w1;  r.y = A11.y * n1 + B11.y * w1;
        r.z = A11.z * n1 + B11.z * w1;  r.w = A11.w * n1 + B11.w * w1;
        s0[D4C + lane + 32] = r;

        if (lane < D4C - 64) {
            const float4 A02 = ea0[lane + 64];
            const float4 B02 = eb0[lane + 64];
            const float4 A12 = ea1[lane + 64];
            const float4 B12 = eb1[lane + 64];
            float4 t;
            t.x = A02.x * n0 + B02.x * w0;  t.y = A02.y * n0 + B02.y * w0;
            t.z = A02.z * n0 + B02.z * w0;  t.w = A02.w * n0 + B02.w * w0;
            s0[lane + 64] = t;
            t.x = A12.x * n1 + B12.x * w1;  t.y = A12.y * n1 + B12.y * w1;
            t.z = A12.z * n1 + B12.z * w1;  t.w = A12.w * n1 + B12.w * w1;
            s0[D4C + lane + 64] = t;
        }
    }

    __syncthreads();
    // Make generic-proxy smem writes visible to the async proxy, then drain
    // the whole 24 KB chunk with one bulk store.
    asm volatile("fence.proxy.async.shared::cta;" ::: "memory");
    if (tid == 0) {
        uint32_t sptr = (uint32_t)__cvta_generic_to_shared(buf);
        const float4* gdst = out + (size_t)blockIdx.x * CHUNK_F4;
        asm volatile(
            "cp.async.bulk.global.shared::cta.bulk_group [%0], [%1], %2;"
            :: "l"(gdst), "r"(sptr), "r"((uint32_t)(CHUNK_F4 * 16))
            : "memory");
        asm volatile("cp.async.bulk.commit_group;" ::: "memory");
        // CTA stays resident (smem pinned) until the bulk op has finished
        // reading shared memory.
        asm volatile("cp.async.bulk.wait_group.read 0;" ::: "memory");
    }
}

extern "C" void kernel_launch(void* const* d_in, const int* in_sizes, int n_in,
                              void* d_out, int out_size)
{
    const float4* emb     = (const float4*)d_in[0];  // emb_table [36, 300] f32
    const float4* pad     = (const float4*)d_in[1];  // pad_table [1, 300] f32
    const int*    tokens  = (const int*)d_in[2];     // tokens [32768, 24] i32
    const int*    lengths = (const int*)d_in[3];     // lengths [32768] i32
    float4*       out     = (float4*)d_out;          // [32768, 10, 300] f32

    const int blocks = BB / ELEMS_PER_CTA;           // 16384 (exact)
    word_emb_kernel<<<blocks, 320>>>(emb, pad, tokens, lengths, out);
}